// round 1
// baseline (speedup 1.0000x reference)
#include <cuda_runtime.h>

#define BB 16
#define NN 1024
#define HH 768
#define H4 (HH/4)          // 192 float4 per row
#define NEG_INF_F (-9000000000000000.0f)
#define SLOPE_F 0.2f

// ---- device scratch (no allocations allowed) ----
__device__ __align__(16) float g_u1[HH];
__device__ __align__(16) float g_u2[HH];
__device__ float g_s1[BB * NN];
__device__ float g_s2[BB * NN];

// ---------------------------------------------------------------------------
// u1 = W @ a[:H], u2 = W @ a[H:]   (tiny: 768x768 dots)
// ---------------------------------------------------------------------------
__global__ void compute_u_kernel(const float* __restrict__ W,
                                 const float* __restrict__ a) {
    int g = blockIdx.x * blockDim.x + threadIdx.x;
    if (g >= HH) return;
    const float* wr = W + (size_t)g * HH;
    float u1 = 0.f, u2 = 0.f;
#pragma unroll 8
    for (int f = 0; f < HH; ++f) {
        float w = wr[f];
        u1 += w * a[f];
        u2 += w * a[HH + f];
    }
    g_u1[g] = u1;
    g_u2[g] = u2;
}

// ---------------------------------------------------------------------------
// node_vec[b,i,:] = sum_{j : adj[b,i,j] != 0} x[b,j,:]
// One block per (b,i) row. Warp 0 builds the (ordered, deterministic) nonzero
// index list via ballot-compaction, then all 192 threads gather-sum float4s.
// ---------------------------------------------------------------------------
__global__ void gather_nv_kernel(const float* __restrict__ x,
                                 const float* __restrict__ adj,
                                 float* __restrict__ nv) {
    __shared__ int s_idx[NN];
    __shared__ int s_cnt;

    const int row = blockIdx.x;           // b*N + i
    const int b = row >> 10;
    const float* arow = adj + (size_t)row * NN;

    const int wid = threadIdx.x >> 5;
    const int lane = threadIdx.x & 31;

    if (wid == 0) {
        // preload 32 strided values per lane (full row), independent loads
        float v[32];
#pragma unroll
        for (int it = 0; it < 32; ++it) v[it] = arow[it * 32 + lane];
        int cnt = 0;
#pragma unroll
        for (int it = 0; it < 32; ++it) {
            bool p = (v[it] > 1e-6f);
            unsigned m = __ballot_sync(0xffffffffu, p);
            if (p) s_idx[cnt + __popc(m & ((1u << lane) - 1u))] = it * 32 + lane;
            cnt += __popc(m);
        }
        if (lane == 0) s_cnt = cnt;
    }
    __syncthreads();

    const int n = s_cnt;
    const float4* xb = (const float4*)(x + (size_t)b * NN * HH);
    const int h4 = threadIdx.x;            // 0..191

    float4 acc = make_float4(0.f, 0.f, 0.f, 0.f);
    int t = 0;
    for (; t + 4 <= n; t += 4) {
        int j0 = s_idx[t], j1 = s_idx[t + 1], j2 = s_idx[t + 2], j3 = s_idx[t + 3];
        float4 v0 = xb[(size_t)j0 * H4 + h4];
        float4 v1 = xb[(size_t)j1 * H4 + h4];
        float4 v2 = xb[(size_t)j2 * H4 + h4];
        float4 v3 = xb[(size_t)j3 * H4 + h4];
        acc.x += v0.x + v1.x + v2.x + v3.x;
        acc.y += v0.y + v1.y + v2.y + v3.y;
        acc.z += v0.z + v1.z + v2.z + v3.z;
        acc.w += v0.w + v1.w + v2.w + v3.w;
    }
    for (; t < n; ++t) {
        int j = s_idx[t];
        float4 v = xb[(size_t)j * H4 + h4];
        acc.x += v.x; acc.y += v.y; acc.z += v.z; acc.w += v.w;
    }
    ((float4*)(nv + (size_t)row * HH))[h4] = acc;
}

// ---------------------------------------------------------------------------
// s1[row] = node_vec[row,:] . u1 ; s2[row] = node_vec[row,:] . u2
// One warp per row, 8 warps per block.
// ---------------------------------------------------------------------------
__global__ void compute_s_kernel(const float* __restrict__ nv) {
    const int row = blockIdx.x * 8 + (threadIdx.x >> 5);
    const int lane = threadIdx.x & 31;
    const float4* r = (const float4*)(nv + (size_t)row * HH);
    const float4* u1 = (const float4*)g_u1;
    const float4* u2 = (const float4*)g_u2;
    float d1 = 0.f, d2 = 0.f;
#pragma unroll
    for (int k = lane; k < H4; k += 32) {
        float4 v = r[k], w1 = u1[k], w2 = u2[k];
        d1 += v.x * w1.x + v.y * w1.y + v.z * w1.z + v.w * w1.w;
        d2 += v.x * w2.x + v.y * w2.y + v.z * w2.z + v.w * w2.w;
    }
#pragma unroll
    for (int o = 16; o > 0; o >>= 1) {
        d1 += __shfl_down_sync(0xffffffffu, d1, o);
        d2 += __shfl_down_sync(0xffffffffu, d2, o);
    }
    if (lane == 0) {
        g_s1[row] = d1;
        g_s2[row] = d2;
    }
}

// ---------------------------------------------------------------------------
// attn[b,i,:] = softmax_j( valid ? leaky_relu(s1[i]+s2[j]) : NEG_INF )
// One block (256 threads) per row; scores staged in smem.
// ---------------------------------------------------------------------------
__global__ void softmax_kernel(const float* __restrict__ adj,
                               const float* __restrict__ nl,
                               float* __restrict__ attn) {
    __shared__ float sc[NN];
    __shared__ float red[8];
    __shared__ float bcast;

    const int row = blockIdx.x;           // b*N + i
    const int b = row >> 10;
    const int tid = threadIdx.x;

    const float s1i = g_s1[row];
    const float nli = nl[row];
    const float* arow = adj + (size_t)row * NN;
    const float* nlb = nl + (size_t)b * NN;
    const float* s2b = g_s2 + (size_t)b * NN;

    float lmax = NEG_INF_F;
    for (int j = tid; j < NN; j += 256) {
        float score = NEG_INF_F;
        float aij = arow[j];
        if (aij > 1e-6f && nli * nlb[j] > 1e-6f) {
            float z = s1i + s2b[j];
            score = (z > 0.f) ? z : SLOPE_F * z;
        }
        sc[j] = score;
        lmax = fmaxf(lmax, score);
    }
#pragma unroll
    for (int o = 16; o > 0; o >>= 1)
        lmax = fmaxf(lmax, __shfl_xor_sync(0xffffffffu, lmax, o));
    if ((tid & 31) == 0) red[tid >> 5] = lmax;
    __syncthreads();
    if (tid == 0) {
        float m = red[0];
#pragma unroll
        for (int k = 1; k < 8; ++k) m = fmaxf(m, red[k]);
        bcast = m;
    }
    __syncthreads();
    const float m = bcast;

    float lsum = 0.f;
    for (int j = tid; j < NN; j += 256) {
        float e = __expf(sc[j] - m);
        sc[j] = e;
        lsum += e;
    }
#pragma unroll
    for (int o = 16; o > 0; o >>= 1)
        lsum += __shfl_xor_sync(0xffffffffu, lsum, o);
    if ((tid & 31) == 0) red[tid >> 5] = lsum;
    __syncthreads();
    if (tid == 0) {
        float s = 0.f;
#pragma unroll
        for (int k = 0; k < 8; ++k) s += red[k];
        bcast = 1.0f / s;
    }
    __syncthreads();
    const float inv = bcast;

    float* orow = attn + (size_t)row * NN;
    for (int j = tid; j < NN; j += 256)
        orow[j] = sc[j] * inv;
}

// ---------------------------------------------------------------------------
extern "C" void kernel_launch(void* const* d_in, const int* in_sizes, int n_in,
                              void* d_out, int out_size) {
    const float* x   = (const float*)d_in[0];  // (B, N, H)
    const float* nl  = (const float*)d_in[1];  // (B, N)
    const float* adj = (const float*)d_in[2];  // (B, N, N)
    const float* W   = (const float*)d_in[3];  // (H, H)
    const float* a   = (const float*)d_in[4];  // (2H, 1)

    float* nv   = (float*)d_out;                       // node_vec: B*N*H
    float* attn = nv + (size_t)BB * NN * HH;           // attn:     B*N*N

    compute_u_kernel<<<(HH + 255) / 256, 256>>>(W, a);
    gather_nv_kernel<<<BB * NN, 192>>>(x, adj, nv);
    compute_s_kernel<<<(BB * NN) / 8, 256>>>(nv);
    softmax_kernel<<<BB * NN, 256>>>(adj, nl, attn);
}